// round 3
// baseline (speedup 1.0000x reference)
#include <cuda_runtime.h>
#include <math.h>

#define Bq 2
#define Lq 1024
#define Aq 14
#define Kq 30
#define NRBF 16
#define NPEq 16
#define EFq 128
#define EDGEIN (NPEq + NRBF*Aq*Aq)   /* 3152 */
#define NKQ4 (EDGEIN/4)              /* 788 float4 chunks along K */
#define NE (Bq*Lq*Kq*EFq)            /* 7864320 */
#define NK (Bq*Lq*Kq)                /* 61440 */

typedef unsigned long long ull;

__device__ int    g_Eidx[Bq*Lq*Kq];
__device__ float4 g_W4[NKQ4*EFq];    /* g_W4[kq*128+f] = {W[f][4kq..4kq+3]} */

// ---------------- packed f32x2 helpers (sm_103a FFMA2 path) ----------------
__device__ __forceinline__ ull fma2(ull a, ull b, ull c){
    ull d; asm("fma.rn.f32x2 %0,%1,%2,%3;" : "=l"(d) : "l"(a),"l"(b),"l"(c)); return d;
}
__device__ __forceinline__ ull mul2(ull a, ull b){
    ull d; asm("mul.rn.f32x2 %0,%1,%2;" : "=l"(d) : "l"(a),"l"(b)); return d;
}
__device__ __forceinline__ ull add2(ull a, ull b){
    ull d; asm("add.rn.f32x2 %0,%1,%2;" : "=l"(d) : "l"(a),"l"(b)); return d;
}
__device__ __forceinline__ ull rep2(float x){
    ull d; asm("mov.b64 %0,{%1,%1};" : "=l"(d) : "f"(x)); return d;
}

// ---------------------------------------------------------------------------
// Prep: W[f][k] -> packed float4 g_W4[kq][f] so weight loads are 4x LDG.128.
// ---------------------------------------------------------------------------
__global__ void pack_W_kernel(const float* __restrict__ W) {
    int idx = blockIdx.x * blockDim.x + threadIdx.x;   // idx = kq*128 + f
    if (idx < NKQ4 * EFq) {
        int kq = idx >> 7, f = idx & 127;
        const float* src = W + f * EDGEIN + kq * 4;
        g_W4[idx] = make_float4(src[0], src[1], src[2], src[3]);
    }
}

// ---------------------------------------------------------------------------
// KNN (unchanged: exact jax top_k(-D) tie-break via (bits<<32)|j packing)
// ---------------------------------------------------------------------------
__global__ void knn_kernel(const float* __restrict__ X,
                           const float* __restrict__ mask,
                           float* __restrict__ outIdxF) {
    const int bi  = blockIdx.x;
    const int b   = bi / Lq;
    const int tid = threadIdx.x;

    __shared__ float sD[Lq];
    __shared__ float smax[8];
    __shared__ unsigned long long red[8];

    const float mi  = mask[bi];
    const float xi0 = X[(bi*Aq + 1)*3 + 0];
    const float xi1 = X[(bi*Aq + 1)*3 + 1];
    const float xi2 = X[(bi*Aq + 1)*3 + 2];

    float lmax = 0.f;
    for (int j = tid; j < Lq; j += 256) {
        const float* xj = X + ((b*Lq + j)*Aq + 1)*3;
        float dx = xi0 - xj[0], dy = xi1 - xj[1], dz = xi2 - xj[2];
        float m2 = mi * mask[b*Lq + j];
        float D  = m2 * sqrtf(dx*dx + dy*dy + dz*dz + 1e-6f);
        sD[j] = D;
        lmax = fmaxf(lmax, D);
    }
    #pragma unroll
    for (int o = 16; o > 0; o >>= 1)
        lmax = fmaxf(lmax, __shfl_xor_sync(0xffffffffu, lmax, o));
    if ((tid & 31) == 0) smax[tid >> 5] = lmax;
    __syncthreads();
    float Dmax = smax[0];
    #pragma unroll
    for (int w = 1; w < 8; w++) Dmax = fmaxf(Dmax, smax[w]);

    for (int j = tid; j < Lq; j += 256) {
        float m2 = mi * mask[b*Lq + j];
        sD[j] += 2.f * (1.f - m2) * Dmax;
    }
    __syncthreads();

    for (int k = 0; k < Kq; k++) {
        unsigned long long best = 0xffffffffffffffffull;
        for (int j = tid; j < Lq; j += 256) {
            unsigned long long p =
                (((unsigned long long)__float_as_uint(sD[j])) << 32) | (unsigned)j;
            best = (p < best) ? p : best;
        }
        #pragma unroll
        for (int o = 16; o > 0; o >>= 1) {
            unsigned long long other = __shfl_xor_sync(0xffffffffu, best, o);
            best = (other < best) ? other : best;
        }
        if ((tid & 31) == 0) red[tid >> 5] = best;
        __syncthreads();
        if (tid == 0) {
            unsigned long long bb = red[0];
            #pragma unroll
            for (int w = 1; w < 8; w++) bb = (red[w] < bb) ? red[w] : bb;
            int j = (int)(bb & 0xffffffffull);
            g_Eidx[bi*Kq + k] = j;
            if (outIdxF) outIdxF[bi*Kq + k] = (float)j;
            sD[j] = __int_as_float(0x7f800000);
        }
        __syncthreads();
    }
}

// ---------------------------------------------------------------------------
__device__ __forceinline__ void loadX2(const float* __restrict__ Xres, int a, float* out3) {
    if (a == 4) {  // virtual Cb
        float Nx = Xres[0], Ny = Xres[1], Nz = Xres[2];
        float Cax= Xres[3], Cay= Xres[4], Caz= Xres[5];
        float Cx = Xres[6], Cy = Xres[7], Cz = Xres[8];
        float bx = Cax - Nx, by = Cay - Ny, bz = Caz - Nz;
        float cx = Cx - Cax, cy = Cy - Cay, cz = Cz - Caz;
        float ax = by*cz - bz*cy;
        float ay = bz*cx - bx*cz;
        float az = bx*cy - by*cx;
        out3[0] = -0.58273431f*ax + 0.56802827f*bx - 0.54067466f*cx + Cax;
        out3[1] = -0.58273431f*ay + 0.56802827f*by - 0.54067466f*cy + Cay;
        out3[2] = -0.58273431f*az + 0.56802827f*bz - 0.54067466f*cz + Caz;
    } else {
        out3[0] = Xres[a*3+0];
        out3[1] = Xres[a*3+1];
        out3[2] = Xres[a*3+2];
    }
}

// ---------------------------------------------------------------------------
// Edge features + GEMM (f32x2-packed, compacted-sparse) + LayerNorm.
// One block per (b,i) row, 128 threads (thread = output feature f).
// ---------------------------------------------------------------------------
__global__ __launch_bounds__(128) void edge_kernel(
    const float* __restrict__ X,
    const float* __restrict__ atom_mask,
    const float* __restrict__ gamma,
    const float* __restrict__ beta,
    float* __restrict__ outE) {

    const int bi = blockIdx.x;
    const int b  = bi / Lq, i = bi % Lq;
    const int tid = threadIdx.x;
    const int f = tid;

    __shared__ __align__(16) float Fa[7][15][NRBF][2];   // half-slab, pair-interleaved
    __shared__ __align__(16) float acc_s[15][EFq][2];    // accum pairs [ep][f][{e0,e1}]
    __shared__ __align__(16) float Epos[Kq][NPEq];
    __shared__ float X2i[Aq][3];
    __shared__ float X2n[Kq][Aq][3];
    __shared__ float ami[Aq];
    __shared__ float amn[Kq][Aq];
    __shared__ int   jn[Kq];
    __shared__ int   elist[Aq][15];
    __shared__ int   ecnt[Aq];
    __shared__ float sg[EFq], sb[EFq];

    if (tid < Kq) jn[tid] = g_Eidx[bi*Kq + tid];
    if (tid < Aq) {
        loadX2(X + bi*Aq*3, tid, X2i[tid]);
        ami[tid] = 1.0f - atom_mask[bi*Aq + tid];
    }
    sg[tid] = gamma[tid];
    sb[tid] = beta[tid];
    __syncthreads();

    for (int t = tid; t < Kq*Aq; t += 128) {
        int e = t / Aq, a = t % Aq;
        int j = jn[e];
        loadX2(X + (b*Lq + j)*Aq*3, a, X2n[e][a]);
        amn[e][a] = 1.0f - atom_mask[(b*Lq + j)*Aq + a];
    }
    __syncthreads();

    // compacted active-pair lists per neighbor-atom b2 (independent of a)
    if (tid < Aq) {
        int c = 0;
        for (int ep = 0; ep < 15; ep++) {
            if (amn[2*ep][tid] != 0.f || amn[2*ep+1][tid] != 0.f)
                elist[tid][c++] = ep;
        }
        ecnt[tid] = c;
    }
    // positional encoding
    for (int t = tid; t < Kq*NPEq; t += 128) {
        int e = t / NPEq, p = t % NPEq;
        float d  = (float)jn[e] - (float)i;
        int   pp = p & 7;
        float fr = expf((float)(2*pp) * -0.57564627324851148f); // -ln(1e4)/16
        float ang = d * fr;
        Epos[e][p] = (p < 8) ? cosf(ang) : sinf(ang);
    }
    __syncthreads();

    // ---- PE chunk: initialize accumulators (all 30 e active) ----
    {
        float4 w0 = g_W4[0*EFq + f];
        float4 w1 = g_W4[1*EFq + f];
        float4 w2 = g_W4[2*EFq + f];
        float4 w3 = g_W4[3*EFq + f];
        #pragma unroll
        for (int e = 0; e < Kq; e++) {
            const float4* vp = (const float4*)Epos[e];
            float4 a0 = vp[0], a1 = vp[1], a2 = vp[2], a3 = vp[3];
            float p0 = w0.x*a0.x; p0 = fmaf(w1.x, a1.x, p0); p0 = fmaf(w2.x, a2.x, p0); p0 = fmaf(w3.x, a3.x, p0);
            float p1 = w0.y*a0.y; p1 = fmaf(w1.y, a1.y, p1); p1 = fmaf(w2.y, a2.y, p1); p1 = fmaf(w3.y, a3.y, p1);
            float p2 = w0.z*a0.z; p2 = fmaf(w1.z, a1.z, p2); p2 = fmaf(w2.z, a2.z, p2); p2 = fmaf(w3.z, a3.z, p2);
            float p3 = w0.w*a0.w; p3 = fmaf(w1.w, a1.w, p3); p3 = fmaf(w2.w, a2.w, p3); p3 = fmaf(w3.w, a3.w, p3);
            acc_s[e >> 1][f][e & 1] = (p0 + p1) + (p2 + p3);
        }
    }
    __syncthreads();

    // ---- RBF chunks ----
    for (int a = 0; a < Aq; a++) {
        if (ami[a] == 0.f) continue;              // block-uniform skip
        const float xa0 = X2i[a][0], xa1 = X2i[a][1], xa2 = X2i[a][2];

        for (int half = 0; half < 2; half++) {
            const int b2base = half * 7;

            // produce half-slab: Fa[b2l][ep][r][e&1]
            for (int t = tid; t < Kq*7; t += 128) {
                int e = t / 7, b2l = t % 7;
                int b2 = b2base + b2l;
                float* dst = &Fa[b2l][e >> 1][0][e & 1];
                if (amn[e][b2] != 0.f) {
                    float dx = xa0 - X2n[e][b2][0];
                    float dy = xa1 - X2n[e][b2][1];
                    float dz = xa2 - X2n[e][b2][2];
                    float D  = sqrtf(dx*dx + dy*dy + dz*dz + 1e-6f);
                    #pragma unroll
                    for (int r = 0; r < NRBF; r++) {
                        float x = (D - (float)r * (20.f/15.f)) * 0.8f;
                        dst[2*r] = __expf(-x*x);
                    }
                } else {
                    #pragma unroll
                    for (int r = 0; r < NRBF; r++) dst[2*r] = 0.f;
                }
            }
            __syncthreads();

            // consume: packed f32x2 dot over compacted active pairs
            for (int b2l = 0; b2l < 7; b2l++) {
                const int b2  = b2base + b2l;
                const int kq0 = 4 + (a*Aq + b2)*4;
                float4 w0 = g_W4[(kq0+0)*EFq + f];
                float4 w1 = g_W4[(kq0+1)*EFq + f];
                float4 w2 = g_W4[(kq0+2)*EFq + f];
                float4 w3 = g_W4[(kq0+3)*EFq + f];
                ull W2[16];
                W2[0]=rep2(w0.x); W2[1]=rep2(w0.y); W2[2]=rep2(w0.z); W2[3]=rep2(w0.w);
                W2[4]=rep2(w1.x); W2[5]=rep2(w1.y); W2[6]=rep2(w1.z); W2[7]=rep2(w1.w);
                W2[8]=rep2(w2.x); W2[9]=rep2(w2.y); W2[10]=rep2(w2.z); W2[11]=rep2(w2.w);
                W2[12]=rep2(w3.x); W2[13]=rep2(w3.y); W2[14]=rep2(w3.z); W2[15]=rep2(w3.w);

                const int cn = ecnt[b2];
                const ull* fa = (const ull*)&Fa[b2l][0][0][0];   // 16 ull per ep
                for (int idx = 0; idx < cn; idx++) {
                    const int ep = elist[b2][idx];
                    const ulonglong2* m = (const ulonglong2*)(fa + (ep << 4));
                    ulonglong2 q0 = m[0], q1 = m[1], q2 = m[2], q3 = m[3];
                    ulonglong2 q4 = m[4], q5 = m[5], q6 = m[6], q7 = m[7];
                    ull acc = *(const ull*)&acc_s[ep][f][0];
                    ull p0 = fma2(q0.x, W2[0], acc);
                    ull p1 = mul2(q0.y, W2[1]);
                    ull p2 = mul2(q1.x, W2[2]);
                    ull p3 = mul2(q1.y, W2[3]);
                    p0 = fma2(q2.x, W2[4],  p0);
                    p1 = fma2(q2.y, W2[5],  p1);
                    p2 = fma2(q3.x, W2[6],  p2);
                    p3 = fma2(q3.y, W2[7],  p3);
                    p0 = fma2(q4.x, W2[8],  p0);
                    p1 = fma2(q4.y, W2[9],  p1);
                    p2 = fma2(q5.x, W2[10], p2);
                    p3 = fma2(q5.y, W2[11], p3);
                    p0 = fma2(q6.x, W2[12], p0);
                    p1 = fma2(q6.y, W2[13], p1);
                    p2 = fma2(q7.x, W2[14], p2);
                    p3 = fma2(q7.y, W2[15], p3);
                    *(ull*)&acc_s[ep][f][0] = add2(add2(p0, p1), add2(p2, p3));
                }
            }
            __syncthreads();
        }
    }

    // ---- LayerNorm: one warp per E-row, single barrier already passed ----
    const int wid = tid >> 5, lid = tid & 31;
    float* outRow = outE + (size_t)bi * (Kq*EFq);
    for (int e = wid; e < Kq; e += 4) {
        const int ep = e >> 1, par = e & 1;
        float v0 = acc_s[ep][lid      ][par];
        float v1 = acc_s[ep][lid + 32 ][par];
        float v2 = acc_s[ep][lid + 64 ][par];
        float v3 = acc_s[ep][lid + 96 ][par];
        float s  = (v0 + v1) + (v2 + v3);
        float sq = fmaf(v0,v0, fmaf(v1,v1, fmaf(v2,v2, v3*v3)));
        #pragma unroll
        for (int o = 16; o > 0; o >>= 1) {
            s  += __shfl_xor_sync(0xffffffffu, s,  o);
            sq += __shfl_xor_sync(0xffffffffu, sq, o);
        }
        float mean = s * (1.f/EFq);
        float var  = sq * (1.f/EFq) - mean*mean;
        float rstd = rsqrtf(var + 1e-5f);
        float* o0 = outRow + e*EFq;
        o0[lid     ] = (v0 - mean) * rstd * sg[lid     ] + sb[lid     ];
        o0[lid + 32] = (v1 - mean) * rstd * sg[lid + 32] + sb[lid + 32];
        o0[lid + 64] = (v2 - mean) * rstd * sg[lid + 64] + sb[lid + 64];
        o0[lid + 96] = (v3 - mean) * rstd * sg[lid + 96] + sb[lid + 96];
    }
}

// ---------------------------------------------------------------------------
extern "C" void kernel_launch(void* const* d_in, const int* in_sizes, int n_in,
                              void* d_out, int out_size) {
    const float* X         = (const float*)d_in[0];
    const float* mask      = (const float*)d_in[1];
    const float* atom_mask = (const float*)d_in[4];
    const float* W         = (const float*)d_in[5];
    const float* gamma     = (const float*)d_in[6];
    const float* beta      = (const float*)d_in[7];

    float* outE   = (float*)d_out;
    float* outIdx = (out_size >= NE + NK) ? (outE + NE) : nullptr;

    pack_W_kernel<<<(NKQ4*EFq + 255)/256, 256>>>(W);
    knn_kernel<<<Bq*Lq, 256>>>(X, mask, outIdx);
    edge_kernel<<<Bq*Lq, 128>>>(X, atom_mask, gamma, beta, outE);
}

// round 4
// speedup vs baseline: 1.2144x; 1.2144x over previous
#include <cuda_runtime.h>
#include <math.h>

#define Bq 2
#define Lq 1024
#define Aq 14
#define Kq 30
#define NRBF 16
#define NPEq 16
#define EFq 128
#define EDGEIN (NPEq + NRBF*Aq*Aq)   /* 3152 */
#define NKQ4 (EDGEIN/4)              /* 788 */
#define NE (Bq*Lq*Kq*EFq)
#define NK (Bq*Lq*Kq)
#define PADF 36                      /* floats per (b2,ep) slot: 32 data + 4 pad = 144B */

typedef unsigned long long ull;

__device__ int    g_Eidx[Bq*Lq*Kq];
__device__ float4 g_W4[NKQ4*EFq];    /* g_W4[kq*128+f] = {W[f][4kq..4kq+3]} */

// ---------------- packed f32x2 helpers ----------------
__device__ __forceinline__ ull fma2(ull a, ull b, ull c){
    ull d; asm("fma.rn.f32x2 %0,%1,%2,%3;" : "=l"(d) : "l"(a),"l"(b),"l"(c)); return d;
}
__device__ __forceinline__ ull mul2(ull a, ull b){
    ull d; asm("mul.rn.f32x2 %0,%1,%2;" : "=l"(d) : "l"(a),"l"(b)); return d;
}
__device__ __forceinline__ ull add2(ull a, ull b){
    ull d; asm("add.rn.f32x2 %0,%1,%2;" : "=l"(d) : "l"(a),"l"(b)); return d;
}
__device__ __forceinline__ ull rep2(float x){
    ull d; asm("mov.b64 %0,{%1,%1};" : "=l"(d) : "f"(x)); return d;
}
__device__ __forceinline__ ull pack2(float lo, float hi){
    ull d; asm("mov.b64 %0,{%1,%2};" : "=l"(d) : "f"(lo),"f"(hi)); return d;
}
__device__ __forceinline__ void unpack2(ull v, float& lo, float& hi){
    asm("mov.b64 {%0,%1},%2;" : "=f"(lo),"=f"(hi) : "l"(v));
}

// ---------------------------------------------------------------------------
__global__ void pack_W_kernel(const float* __restrict__ W) {
    int idx = blockIdx.x * blockDim.x + threadIdx.x;
    if (idx < NKQ4 * EFq) {
        int kq = idx >> 7, f = idx & 127;
        const float* src = W + f * EDGEIN + kq * 4;
        g_W4[idx] = make_float4(src[0], src[1], src[2], src[3]);
    }
}

// ---------------------------------------------------------------------------
// KNN (exact jax top_k(-D) tie-break)
// ---------------------------------------------------------------------------
__global__ void knn_kernel(const float* __restrict__ X,
                           const float* __restrict__ mask,
                           float* __restrict__ outIdxF) {
    const int bi  = blockIdx.x;
    const int b   = bi / Lq;
    const int tid = threadIdx.x;

    __shared__ float sD[Lq];
    __shared__ float smax[8];
    __shared__ unsigned long long red[8];

    const float mi  = mask[bi];
    const float xi0 = X[(bi*Aq + 1)*3 + 0];
    const float xi1 = X[(bi*Aq + 1)*3 + 1];
    const float xi2 = X[(bi*Aq + 1)*3 + 2];

    float lmax = 0.f;
    for (int j = tid; j < Lq; j += 256) {
        const float* xj = X + ((b*Lq + j)*Aq + 1)*3;
        float dx = xi0 - xj[0], dy = xi1 - xj[1], dz = xi2 - xj[2];
        float m2 = mi * mask[b*Lq + j];
        float D  = m2 * sqrtf(dx*dx + dy*dy + dz*dz + 1e-6f);
        sD[j] = D;
        lmax = fmaxf(lmax, D);
    }
    #pragma unroll
    for (int o = 16; o > 0; o >>= 1)
        lmax = fmaxf(lmax, __shfl_xor_sync(0xffffffffu, lmax, o));
    if ((tid & 31) == 0) smax[tid >> 5] = lmax;
    __syncthreads();
    float Dmax = smax[0];
    #pragma unroll
    for (int w = 1; w < 8; w++) Dmax = fmaxf(Dmax, smax[w]);

    for (int j = tid; j < Lq; j += 256) {
        float m2 = mi * mask[b*Lq + j];
        sD[j] += 2.f * (1.f - m2) * Dmax;
    }
    __syncthreads();

    for (int k = 0; k < Kq; k++) {
        unsigned long long best = 0xffffffffffffffffull;
        for (int j = tid; j < Lq; j += 256) {
            unsigned long long p =
                (((unsigned long long)__float_as_uint(sD[j])) << 32) | (unsigned)j;
            best = (p < best) ? p : best;
        }
        #pragma unroll
        for (int o = 16; o > 0; o >>= 1) {
            unsigned long long other = __shfl_xor_sync(0xffffffffu, best, o);
            best = (other < best) ? other : best;
        }
        if ((tid & 31) == 0) red[tid >> 5] = best;
        __syncthreads();
        if (tid == 0) {
            unsigned long long bb = red[0];
            #pragma unroll
            for (int w = 1; w < 8; w++) bb = (red[w] < bb) ? red[w] : bb;
            int j = (int)(bb & 0xffffffffull);
            g_Eidx[bi*Kq + k] = j;
            if (outIdxF) outIdxF[bi*Kq + k] = (float)j;
            sD[j] = __int_as_float(0x7f800000);
        }
        __syncthreads();
    }
}

// ---------------------------------------------------------------------------
__device__ __forceinline__ void loadX2(const float* __restrict__ Xres, int a, float* out3) {
    if (a == 4) {  // virtual Cb
        float Nx = Xres[0], Ny = Xres[1], Nz = Xres[2];
        float Cax= Xres[3], Cay= Xres[4], Caz= Xres[5];
        float Cx = Xres[6], Cy = Xres[7], Cz = Xres[8];
        float bx = Cax - Nx, by = Cay - Ny, bz = Caz - Nz;
        float cx = Cx - Cax, cy = Cy - Cay, cz = Cz - Caz;
        float ax = by*cz - bz*cy;
        float ay = bz*cx - bx*cz;
        float az = bx*cy - by*cx;
        out3[0] = -0.58273431f*ax + 0.56802827f*bx - 0.54067466f*cx + Cax;
        out3[1] = -0.58273431f*ay + 0.56802827f*by - 0.54067466f*cy + Cay;
        out3[2] = -0.58273431f*az + 0.56802827f*bz - 0.54067466f*cz + Caz;
    } else {
        out3[0] = Xres[a*3+0];
        out3[1] = Xres[a*3+1];
        out3[2] = Xres[a*3+2];
    }
}

// ---------------------------------------------------------------------------
// Fused edge kernel: dense-e, register acc pairs, FFMA2, branch-free consume.
// Block = one (b,i) residue, 128 threads, thread = output feature f.
// ---------------------------------------------------------------------------
__global__ __launch_bounds__(128) void edge_kernel(
    const float* __restrict__ X,
    const float* __restrict__ atom_mask,
    const float* __restrict__ gamma,
    const float* __restrict__ beta,
    float* __restrict__ outE) {

    const int bi = blockIdx.x;
    const int b  = bi / Lq, i = bi % Lq;
    const int tid = threadIdx.x;
    const int f = tid;

    __shared__ __align__(16) float Fa[Aq][15][PADF];   // 30.2 KB feature slab (for one a)
    __shared__ __align__(16) float Epos[Kq][NPEq];
    __shared__ float X2i[Aq][3];
    __shared__ float X2n[Kq][Aq][3];
    __shared__ float ami[Aq];
    __shared__ float amn[Kq][Aq];
    __shared__ int   jn[Kq];
    __shared__ float sg[EFq], sb[EFq];

    if (tid < Kq) jn[tid] = g_Eidx[bi*Kq + tid];
    if (tid < Aq) {
        loadX2(X + bi*Aq*3, tid, X2i[tid]);
        ami[tid] = 1.0f - atom_mask[bi*Aq + tid];
    }
    sg[tid] = gamma[tid];
    sb[tid] = beta[tid];
    __syncthreads();

    for (int t = tid; t < Kq*Aq; t += 128) {
        int e = t / Aq, a = t % Aq;
        int j = jn[e];
        loadX2(X + (b*Lq + j)*Aq*3, a, X2n[e][a]);
        amn[e][a] = 1.0f - atom_mask[(b*Lq + j)*Aq + a];
    }
    // positional encoding
    for (int t = tid; t < Kq*NPEq; t += 128) {
        int e = t / NPEq, p = t % NPEq;
        float d  = (float)jn[e] - (float)i;
        int   pp = p & 7;
        float fr = expf((float)(2*pp) * -0.57564627324851148f); // -ln(1e4)/16
        float ang = d * fr;
        Epos[e][p] = (p < 8) ? cosf(ang) : sinf(ang);
    }
    __syncthreads();

    // ---- PE chunk: init acc pairs (e-pair packed) ----
    ull acc[15];
    {
        float4 w0 = g_W4[0*EFq + f];
        float4 w1 = g_W4[1*EFq + f];
        float4 w2 = g_W4[2*EFq + f];
        float4 w3 = g_W4[3*EFq + f];
        #pragma unroll
        for (int ep = 0; ep < 15; ep++) {
            float pv[2];
            #pragma unroll
            for (int h = 0; h < 2; h++) {
                const float4* vp = (const float4*)Epos[2*ep + h];
                float4 a0 = vp[0], a1 = vp[1], a2 = vp[2], a3 = vp[3];
                float p0 = w0.x*a0.x; p0 = fmaf(w1.x, a1.x, p0); p0 = fmaf(w2.x, a2.x, p0); p0 = fmaf(w3.x, a3.x, p0);
                float p1 = w0.y*a0.y; p1 = fmaf(w1.y, a1.y, p1); p1 = fmaf(w2.y, a2.y, p1); p1 = fmaf(w3.y, a3.y, p1);
                float p2 = w0.z*a0.z; p2 = fmaf(w1.z, a1.z, p2); p2 = fmaf(w2.z, a2.z, p2); p2 = fmaf(w3.z, a3.z, p2);
                float p3 = w0.w*a0.w; p3 = fmaf(w1.w, a1.w, p3); p3 = fmaf(w2.w, a2.w, p3); p3 = fmaf(w3.w, a3.w, p3);
                pv[h] = (p0 + p1) + (p2 + p3);
            }
            acc[ep] = pack2(pv[0], pv[1]);
        }
    }

    // ---- RBF: loop atoms a (block-uniform skip), produce slab, consume dense ----
    for (int a = 0; a < Aq; a++) {
        if (ami[a] == 0.f) continue;
        const float xa0 = X2i[a][0], xa1 = X2i[a][1], xa2 = X2i[a][2];

        __syncthreads();   // previous consumption finished before overwrite
        // produce Fa[b2][ep][r-pairs] for this a (zeros where combo==0)
        for (int t = tid; t < 15*Aq; t += 128) {
            int ep = t / Aq, b2 = t % Aq;
            float2* slot = (float2*)&Fa[b2][ep][0];
            float v[2][NRBF];
            #pragma unroll
            for (int h = 0; h < 2; h++) {
                int e = 2*ep + h;
                if (amn[e][b2] != 0.f) {
                    float dx = xa0 - X2n[e][b2][0];
                    float dy = xa1 - X2n[e][b2][1];
                    float dz = xa2 - X2n[e][b2][2];
                    float D  = sqrtf(dx*dx + dy*dy + dz*dz + 1e-6f);
                    #pragma unroll
                    for (int r = 0; r < NRBF; r++) {
                        float x = (D - (float)r * (20.f/15.f)) * 0.8f;
                        v[h][r] = __expf(-x*x);
                    }
                } else {
                    #pragma unroll
                    for (int r = 0; r < NRBF; r++) v[h][r] = 0.f;
                }
            }
            #pragma unroll
            for (int r = 0; r < NRBF; r++) slot[r] = make_float2(v[0][r], v[1][r]);
        }
        __syncthreads();

        // consume: dense e, branch-free, packed FFMA2
        for (int b2 = 0; b2 < Aq; b2++) {
            const int kq0 = 4 + (a*Aq + b2)*4;
            float4 w0 = g_W4[(kq0+0)*EFq + f];
            float4 w1 = g_W4[(kq0+1)*EFq + f];
            float4 w2 = g_W4[(kq0+2)*EFq + f];
            float4 w3 = g_W4[(kq0+3)*EFq + f];
            ull Wa = rep2(w0.x), Wb = rep2(w0.y), Wc = rep2(w0.z), Wd = rep2(w0.w);
            ull We = rep2(w1.x), Wf = rep2(w1.y), Wg = rep2(w1.z), Wh = rep2(w1.w);
            ull Wi = rep2(w2.x), Wj = rep2(w2.y), Wk = rep2(w2.z), Wl = rep2(w2.w);
            ull Wm = rep2(w3.x), Wn = rep2(w3.y), Wo = rep2(w3.z), Wp = rep2(w3.w);
            #pragma unroll
            for (int ep = 0; ep < 15; ep++) {
                const ulonglong2* m = (const ulonglong2*)&Fa[b2][ep][0]; // broadcast
                ulonglong2 q0 = m[0], q1 = m[1], q2 = m[2], q3 = m[3];
                ulonglong2 q4 = m[4], q5 = m[5], q6 = m[6], q7 = m[7];
                ull A = fma2(q0.x, Wa, acc[ep]);
                ull Bv = mul2(q0.y, Wb);
                A  = fma2(q1.x, Wc, A);  Bv = fma2(q1.y, Wd, Bv);
                A  = fma2(q2.x, We, A);  Bv = fma2(q2.y, Wf, Bv);
                A  = fma2(q3.x, Wg, A);  Bv = fma2(q3.y, Wh, Bv);
                A  = fma2(q4.x, Wi, A);  Bv = fma2(q4.y, Wj, Bv);
                A  = fma2(q5.x, Wk, A);  Bv = fma2(q5.y, Wl, Bv);
                A  = fma2(q6.x, Wm, A);  Bv = fma2(q6.y, Wn, Bv);
                A  = fma2(q7.x, Wo, A);  Bv = fma2(q7.y, Wp, Bv);
                acc[ep] = add2(A, Bv);
            }
        }
    }

    // ---- dump acc pairs to smem (alias Fa), then LayerNorm ----
    __syncthreads();
    float* accout = &Fa[0][0][0];       // [ep][f][2] = 15*128*2 floats (< Fa size)
    #pragma unroll
    for (int ep = 0; ep < 15; ep++) {
        float lo, hi; unpack2(acc[ep], lo, hi);
        *(float2*)&accout[(ep*EFq + f)*2] = make_float2(lo, hi);
    }
    __syncthreads();

    const int wid = tid >> 5, lid = tid & 31;
    float* outRow = outE + (size_t)bi * (Kq*EFq);
    for (int e = wid; e < Kq; e += 4) {
        const int ep = e >> 1, par = e & 1;
        const float* ab = &accout[ep*EFq*2 + par];
        float v0 = ab[(lid      )*2];
        float v1 = ab[(lid + 32 )*2];
        float v2 = ab[(lid + 64 )*2];
        float v3 = ab[(lid + 96 )*2];
        float s  = (v0 + v1) + (v2 + v3);
        float sq = fmaf(v0,v0, fmaf(v1,v1, fmaf(v2,v2, v3*v3)));
        #pragma unroll
        for (int o = 16; o > 0; o >>= 1) {
            s  += __shfl_xor_sync(0xffffffffu, s,  o);
            sq += __shfl_xor_sync(0xffffffffu, sq, o);
        }
        float mean = s * (1.f/EFq);
        float var  = sq * (1.f/EFq) - mean*mean;
        float rstd = rsqrtf(var + 1e-5f);
        float* o0 = outRow + e*EFq;
        o0[lid     ] = (v0 - mean) * rstd * sg[lid     ] + sb[lid     ];
        o0[lid + 32] = (v1 - mean) * rstd * sg[lid + 32] + sb[lid + 32];
        o0[lid + 64] = (v2 - mean) * rstd * sg[lid + 64] + sb[lid + 64];
        o0[lid + 96] = (v3 - mean) * rstd * sg[lid + 96] + sb[lid + 96];
    }
}

// ---------------------------------------------------------------------------
extern "C" void kernel_launch(void* const* d_in, const int* in_sizes, int n_in,
                              void* d_out, int out_size) {
    const float* X         = (const float*)d_in[0];
    const float* mask      = (const float*)d_in[1];
    const float* atom_mask = (const float*)d_in[4];
    const float* W         = (const float*)d_in[5];
    const float* gamma     = (const float*)d_in[6];
    const float* beta      = (const float*)d_in[7];

    float* outE   = (float*)d_out;
    float* outIdx = (out_size >= NE + NK) ? (outE + NE) : nullptr;

    pack_W_kernel<<<(NKQ4*EFq + 255)/256, 256>>>(W);
    knn_kernel<<<Bq*Lq, 256>>>(X, mask, outIdx);
    edge_kernel<<<Bq*Lq, 128>>>(X, atom_mask, gamma, beta, outE);
}